// round 1
// baseline (speedup 1.0000x reference)
#include <cuda_runtime.h>

// Problem constants
#define SEQ   2048
#define BATCH 2
#define HID   1024
#define NROWS 4096          // BATCH*SEQ
#define PCOLS 4096          // 8 projections * 512 cols each
// P column layout: [Q(0) K(512) V(1024) LQ(1536) LK1(2048) LK2(2560) LV1(3072) LV2(3584)]

// Scratch (device globals: allocation-free per harness rules)
__device__ float g_P[(size_t)NROWS * PCOLS];          // 64 MB projections
__device__ float g_Mpart[8 * 16 * 64 * 64];           // split-K partials for M
__device__ float g_M[16 * 64 * 64];                   // per (b, local head) lk1^T lk1

struct ProjArgs {
    const float* w[8];
    const float* b[8];
};

// ---------------------------------------------------------------------------
// Kernel 1: fused projection GEMM.  g_P = X[4096,1024] @ Wcat[1024,4096] + bias
// 128x128 block tile, BK=8, 256 threads, 8x8 microtile per thread.
// ---------------------------------------------------------------------------
__global__ __launch_bounds__(256) void proj_gemm(const float* __restrict__ X, ProjArgs pa) {
    __shared__ float As[8 * 128];
    __shared__ float Bs[8 * 128];

    const int bm = blockIdx.y;
    const int bn = blockIdx.x;
    const int widx  = bn >> 2;                 // which of the 8 weight mats
    const int ncol0 = (bn & 3) * 128;          // local col within that W (fan_out=512)
    const float* __restrict__ W    = pa.w[widx];
    const float* __restrict__ bias = pa.b[widx];

    const int tid = threadIdx.x;
    const int tx = tid & 15;                   // col group
    const int ty = tid >> 4;                   // row group

    // load indices
    const int arow = tid >> 1;                 // 0..127
    const int acol = (tid & 1) * 4;            // 0 or 4
    const int brow = tid >> 5;                 // 0..7
    const int bcol = (tid & 31) * 4;           // 0..124

    float acc[8][8];
#pragma unroll
    for (int i = 0; i < 8; i++)
#pragma unroll
        for (int j = 0; j < 8; j++) acc[i][j] = 0.f;

    const float* Aptr = X + (size_t)(bm * 128 + arow) * HID + acol;
    const float* Bptr = W + (size_t)brow * 512 + ncol0 + bcol;

    for (int k0 = 0; k0 < HID; k0 += 8) {
        float4 av = *(const float4*)(Aptr + k0);
        float4 bv = *(const float4*)(Bptr + (size_t)k0 * 512);
        __syncthreads();
        As[(acol + 0) * 128 + arow] = av.x;
        As[(acol + 1) * 128 + arow] = av.y;
        As[(acol + 2) * 128 + arow] = av.z;
        As[(acol + 3) * 128 + arow] = av.w;
        *(float4*)&Bs[brow * 128 + bcol] = bv;
        __syncthreads();
#pragma unroll
        for (int k = 0; k < 8; k++) {
            float ar[8], br[8];
            *(float4*)&ar[0] = *(float4*)&As[k * 128 + ty * 8];
            *(float4*)&ar[4] = *(float4*)&As[k * 128 + ty * 8 + 4];
            *(float4*)&br[0] = *(float4*)&Bs[k * 128 + tx * 8];
            *(float4*)&br[4] = *(float4*)&Bs[k * 128 + tx * 8 + 4];
#pragma unroll
            for (int i = 0; i < 8; i++)
#pragma unroll
                for (int j = 0; j < 8; j++) acc[i][j] += ar[i] * br[j];
        }
    }

    float bb[8];
#pragma unroll
    for (int j = 0; j < 8; j++) bb[j] = bias[ncol0 + tx * 8 + j];

#pragma unroll
    for (int i = 0; i < 8; i++) {
        const int row = bm * 128 + ty * 8 + i;
        float* dst = &g_P[(size_t)row * PCOLS + bn * 128 + tx * 8];
        float4 c0, c1;
        c0.x = acc[i][0] + bb[0]; c0.y = acc[i][1] + bb[1];
        c0.z = acc[i][2] + bb[2]; c0.w = acc[i][3] + bb[3];
        c1.x = acc[i][4] + bb[4]; c1.y = acc[i][5] + bb[5];
        c1.z = acc[i][6] + bb[6]; c1.w = acc[i][7] + bb[7];
        *(float4*)&dst[0] = c0;
        *(float4*)&dst[4] = c1;
    }
}

// ---------------------------------------------------------------------------
// Kernel 2: M partials. M[b,h] = lk1[b,h]^T @ lk1[b,h]  (64x64), split over 8
// sequence chunks for parallelism. grid = (16 bh, 8 parts), 256 threads.
// ---------------------------------------------------------------------------
__global__ __launch_bounds__(256) void compute_M_part() {
    __shared__ float Ls[64 * 68];
    const int bh = blockIdx.x;       // b*8 + h
    const int b  = bh >> 3;
    const int h  = bh & 7;
    const int part = blockIdx.y;
    const int tid = threadIdx.x;
    const int e  = tid & 63;
    const int d0 = tid >> 6;

    float acc[16];
#pragma unroll
    for (int i = 0; i < 16; i++) acc[i] = 0.f;

    const int colbase = 2048 + h * 64;   // LK1 columns
    for (int t = 0; t < 4; t++) {
        const int s0 = (part * 4 + t) * 64;
        __syncthreads();
#pragma unroll
        for (int ch = 0; ch < 4; ch++) {
            int idx = tid + 256 * ch;
            int r = idx >> 4, c4 = (idx & 15) * 4;
            *(float4*)&Ls[r * 68 + c4] =
                *(const float4*)&g_P[(size_t)(b * SEQ + s0 + r) * PCOLS + colbase + c4];
        }
        __syncthreads();
        for (int r = 0; r < 64; r++) {
            const float le = Ls[r * 68 + e];
#pragma unroll
            for (int i = 0; i < 16; i++)
                acc[i] += Ls[r * 68 + d0 + 4 * i] * le;
        }
    }
#pragma unroll
    for (int i = 0; i < 16; i++)
        g_Mpart[((size_t)part * 16 + bh) * 4096 + (d0 + 4 * i) * 64 + e] = acc[i];
}

// Kernel 2b: deterministic fixed-order reduce of the 8 partials.
__global__ __launch_bounds__(256) void reduce_M() {
    const int t = blockIdx.x * 256 + threadIdx.x;   // 0 .. 65535
    const int bh  = t >> 12;
    const int idx = t & 4095;
    float s = 0.f;
#pragma unroll
    for (int p = 0; p < 8; p++)
        s += g_Mpart[((size_t)p * 16 + bh) * 4096 + idx];
    g_M[(size_t)bh * 4096 + idx] = s;
}

// ---------------------------------------------------------------------------
// Kernel 3: LQ' = LQ @ M, in place over the LQ columns of g_P.
// grid = (64 row-blocks of 64, 8 heads), 256 threads.
// ---------------------------------------------------------------------------
__global__ __launch_bounds__(256) void lq_update() {
    __shared__ float Ms[64 * 65];
    __shared__ float Ls[64 * 68];
    const int rb = blockIdx.x;
    const int h  = blockIdx.y;
    const int row0 = rb * 64;
    const int b = row0 >> 11;            // /2048
    const int bh = b * 8 + h;
    const int tid = threadIdx.x;
    const int colbase = 1536 + h * 64;   // LQ columns

#pragma unroll
    for (int ch = 0; ch < 16; ch++) {
        int idx = tid + 256 * ch;
        int d = idx >> 6, e = idx & 63;
        Ms[d * 65 + e] = g_M[(size_t)bh * 4096 + idx];
    }
#pragma unroll
    for (int ch = 0; ch < 4; ch++) {
        int idx = tid + 256 * ch;
        int r = idx >> 4, c4 = (idx & 15) * 4;
        *(float4*)&Ls[r * 68 + c4] =
            *(const float4*)&g_P[(size_t)(row0 + r) * PCOLS + colbase + c4];
    }
    __syncthreads();

    const int e  = tid & 63;
    const int r0 = tid >> 6;
    float acc[16];
#pragma unroll
    for (int i = 0; i < 16; i++) acc[i] = 0.f;
    for (int d = 0; d < 64; d++) {
        const float mv = Ms[d * 65 + e];
#pragma unroll
        for (int i = 0; i < 16; i++)
            acc[i] += Ls[(r0 + 4 * i) * 68 + d] * mv;
    }
#pragma unroll
    for (int i = 0; i < 16; i++)
        g_P[(size_t)(row0 + r0 + 4 * i) * PCOLS + colbase + e] = acc[i];
}

// ---------------------------------------------------------------------------
// Kernel 4: flash attention (both branches).
// grid = (32 q-blocks, B*16 head-slots). BM=BN=64, 256 threads, 4x4 microtile.
// ---------------------------------------------------------------------------
__global__ __launch_bounds__(256) void flash_attn(const float* __restrict__ mask,
                                                  float* __restrict__ out) {
    extern __shared__ float sm[];
    float* Qs = sm;                    // 64*68
    float* Ks = sm + 64 * 68;
    float* Vs = sm + 2 * 64 * 68;
    float* Ps = sm + 3 * 64 * 68;

    const int tid = threadIdx.x;
    const int tx = tid & 15;
    const int ty = tid >> 4;
    const int qb = blockIdx.x;
    const int by = blockIdx.y;
    const int b = by >> 4;
    const int head = by & 15;
    const bool isloc = head >= 8;
    const int lh = head & 7;
    const int qcol  = isloc ? (1536 + lh * 64) : (head * 64);
    const int kcol  = isloc ? (2560 + lh * 64) : (512 + head * 64);
    const int vcol1 = isloc ? (3072 + lh * 64) : (1024 + head * 64);
    const int vcol2 = 3584 + lh * 64;
    const float scale = 0.125f;        // 1/sqrt(64)
    const int rowbase = b * SEQ;

    // Load Q tile
#pragma unroll
    for (int ch = 0; ch < 4; ch++) {
        int idx = tid + 256 * ch;
        int r = idx >> 4, c4 = (idx & 15) * 4;
        *(float4*)&Qs[r * 68 + c4] =
            *(const float4*)&g_P[(size_t)(rowbase + qb * 64 + r) * PCOLS + qcol + c4];
    }

    float o[4][4];
    float m[4], l[4];
#pragma unroll
    for (int i = 0; i < 4; i++) {
        m[i] = -1e30f; l[i] = 0.f;
#pragma unroll
        for (int j = 0; j < 4; j++) o[i][j] = 0.f;
    }

    for (int kt = 0; kt < 32; kt++) {
        __syncthreads();   // prior-iter Ps/Vs reads finished
#pragma unroll
        for (int ch = 0; ch < 4; ch++) {
            int idx = tid + 256 * ch;
            int r = idx >> 4, c4 = (idx & 15) * 4;
            size_t grow = (size_t)(rowbase + kt * 64 + r) * PCOLS;
            *(float4*)&Ks[r * 68 + c4] = *(const float4*)&g_P[grow + kcol + c4];
            float4 v1 = *(const float4*)&g_P[grow + vcol1 + c4];
            if (isloc) {
                float4 v2 = *(const float4*)&g_P[grow + vcol2 + c4];
                v1.x += v2.x; v1.y += v2.y; v1.z += v2.z; v1.w += v2.w;
            }
            *(float4*)&Vs[r * 68 + c4] = v1;
        }
        __syncthreads();

        // S tile: s[i][j] = Q[ty*4+i,:] . K[tx*4+j,:]
        float s[4][4];
#pragma unroll
        for (int i = 0; i < 4; i++)
#pragma unroll
            for (int j = 0; j < 4; j++) s[i][j] = 0.f;
#pragma unroll
        for (int k4 = 0; k4 < 64; k4 += 4) {
            float4 qv[4], kv[4];
#pragma unroll
            for (int i = 0; i < 4; i++)
                qv[i] = *(float4*)&Qs[(ty * 4 + i) * 68 + k4];
#pragma unroll
            for (int j = 0; j < 4; j++)
                kv[j] = *(float4*)&Ks[(tx * 4 + j) * 68 + k4];
#pragma unroll
            for (int i = 0; i < 4; i++)
#pragma unroll
                for (int j = 0; j < 4; j++) {
                    s[i][j] += qv[i].x * kv[j].x;
                    s[i][j] += qv[i].y * kv[j].y;
                    s[i][j] += qv[i].z * kv[j].z;
                    s[i][j] += qv[i].w * kv[j].w;
                }
        }

        float4 mk = make_float4(0.f, 0.f, 0.f, 0.f);
        if (!isloc)
            mk = *(const float4*)&mask[b * SEQ + kt * 64 + tx * 4];
#pragma unroll
        for (int i = 0; i < 4; i++) {
            s[i][0] = s[i][0] * scale + mk.x;
            s[i][1] = s[i][1] * scale + mk.y;
            s[i][2] = s[i][2] * scale + mk.z;
            s[i][3] = s[i][3] * scale + mk.w;
        }

        // online softmax (rows reduced across the 16 tx lanes)
#pragma unroll
        for (int i = 0; i < 4; i++) {
            float mx = fmaxf(fmaxf(s[i][0], s[i][1]), fmaxf(s[i][2], s[i][3]));
#pragma unroll
            for (int off = 1; off < 16; off <<= 1)
                mx = fmaxf(mx, __shfl_xor_sync(0xffffffffu, mx, off));
            const float mnew = fmaxf(m[i], mx);
            const float corr = __expf(m[i] - mnew);
            float ps = 0.f;
            float4 pv;
            pv.x = __expf(s[i][0] - mnew); ps += pv.x;
            pv.y = __expf(s[i][1] - mnew); ps += pv.y;
            pv.z = __expf(s[i][2] - mnew); ps += pv.z;
            pv.w = __expf(s[i][3] - mnew); ps += pv.w;
#pragma unroll
            for (int off = 1; off < 16; off <<= 1)
                ps += __shfl_xor_sync(0xffffffffu, ps, off);
            l[i] = l[i] * corr + ps;
            m[i] = mnew;
            o[i][0] *= corr; o[i][1] *= corr; o[i][2] *= corr; o[i][3] *= corr;
            *(float4*)&Ps[(ty * 4 + i) * 68 + tx * 4] = pv;
        }
        __syncthreads();

        // O += P @ V
        for (int jj = 0; jj < 64; jj++) {
            const float4 vv = *(float4*)&Vs[jj * 68 + tx * 4];
#pragma unroll
            for (int i = 0; i < 4; i++) {
                const float p = Ps[(ty * 4 + i) * 68 + jj];
                o[i][0] += p * vv.x;
                o[i][1] += p * vv.y;
                o[i][2] += p * vv.z;
                o[i][3] += p * vv.w;
            }
        }
    }

    // epilogue
    const int ocol = head * 64 + tx * 4;
#pragma unroll
    for (int i = 0; i < 4; i++) {
        const float inv = 1.0f / l[i];
        const int row = rowbase + qb * 64 + ty * 4 + i;
        float4 ov = make_float4(o[i][0] * inv, o[i][1] * inv, o[i][2] * inv, o[i][3] * inv);
        *(float4*)&out[(size_t)row * HID + ocol] = ov;
    }
}

// ---------------------------------------------------------------------------
extern "C" void kernel_launch(void* const* d_in, const int* in_sizes, int n_in,
                              void* d_out, int out_size) {
    (void)in_sizes; (void)n_in; (void)out_size;
    const float* X    = (const float*)d_in[0];
    const float* mask = (const float*)d_in[1];
    ProjArgs pa;
    for (int i = 0; i < 8; i++) {
        pa.w[i] = (const float*)d_in[2 + 2 * i];
        pa.b[i] = (const float*)d_in[3 + 2 * i];
    }
    float* out = (float*)d_out;

    const int FLASH_SMEM = 4 * 64 * 68 * (int)sizeof(float);   // 69632 B
    cudaFuncSetAttribute(flash_attn, cudaFuncAttributeMaxDynamicSharedMemorySize, FLASH_SMEM);

    proj_gemm<<<dim3(32, 32), 256>>>(X, pa);
    compute_M_part<<<dim3(16, 8), 256>>>();
    reduce_M<<<256, 256>>>();
    lq_update<<<dim3(64, 8), 256>>>();
    flash_attn<<<dim3(32, 32), 256, FLASH_SMEM>>>(mask, out);
}